// round 4
// baseline (speedup 1.0000x reference)
#include <cuda_runtime.h>
#include <mma.h>

using namespace nvcuda;

#define N_NODES 100000
#define HD 128
#define IN_DIM 256
#define LN_EPS 1e-5f

#define TSS 36     // smem tile stride (floats) for 32-wide K tiles, +4 pad
#define CS 132     // epilogue C stride (floats)

// ---------------- scratch (device globals; no allocation allowed) ----------------
__device__ __align__(16) float g_hu[(size_t)N_NODES * HD];
__device__ __align__(16) float g_hi[(size_t)N_NODES * HD];
__device__ __align__(16) float g_agg_u[(size_t)N_NODES * HD];
__device__ __align__(16) float g_agg_i[(size_t)N_NODES * HD];
__device__ __align__(16) float g_cnt_u[N_NODES];
__device__ __align__(16) float g_cnt_i[N_NODES];

typedef wmma::fragment<wmma::matrix_a, 16, 16, 8, wmma::precision::tf32, wmma::row_major> FragA;
typedef wmma::fragment<wmma::matrix_b, 16, 16, 8, wmma::precision::tf32, wmma::col_major> FragB;
typedef wmma::fragment<wmma::accumulator, 16, 16, 8, float> FragC;

// split a float4 into tf32 hi / lo parts
__device__ __forceinline__ void split4(const float4& v, float4& h, float4& l) {
    h.x = wmma::__float_to_tf32(v.x); l.x = wmma::__float_to_tf32(v.x - h.x);
    h.y = wmma::__float_to_tf32(v.y); l.y = wmma::__float_to_tf32(v.y - h.y);
    h.z = wmma::__float_to_tf32(v.z); l.z = wmma::__float_to_tf32(v.z - h.z);
    h.w = wmma::__float_to_tf32(v.w); l.w = wmma::__float_to_tf32(v.w - h.w);
}

// ---------------- zero agg/cnt for a layer ----------------
__global__ void zero_layer_kernel() {
    const size_t n4 = (size_t)N_NODES * HD / 4;
    const float4 z = make_float4(0.f, 0.f, 0.f, 0.f);
    float4* au = (float4*)g_agg_u;
    float4* ai = (float4*)g_agg_i;
    float4* cu = (float4*)g_cnt_u;
    float4* ci = (float4*)g_cnt_i;
    size_t stride = (size_t)gridDim.x * blockDim.x;
    for (size_t i = (size_t)blockIdx.x * blockDim.x + threadIdx.x; i < n4; i += stride) {
        au[i] = z;
        ai[i] = z;
        if (i < N_NODES / 4) { cu[i] = z; ci[i] = z; }
    }
}

// ---------------- edge scatter: warp per edge, vector RED per lane ----------------
__global__ __launch_bounds__(256) void scatter_kernel(
    const int* __restrict__ src, const int* __restrict__ dst, int E, int to_item)
{
    const float* h = to_item ? g_hu : g_hi;   // source features
    float* agg     = to_item ? g_agg_i : g_agg_u;
    float* cnt     = to_item ? g_cnt_i : g_cnt_u;

    int w = (blockIdx.x * blockDim.x + threadIdx.x) >> 5;
    int lane = threadIdx.x & 31;
    if (w >= E) return;
    int s = src[w];
    int d = dst[w];
    float4 v = ((const float4*)(h + (size_t)s * HD))[lane];
    float* ap = agg + (size_t)d * HD + lane * 4;
    asm volatile("red.global.add.v4.f32 [%0], {%1, %2, %3, %4};"
                 :: "l"(ap), "f"(v.x), "f"(v.y), "f"(v.z), "f"(v.w) : "memory");
    if (lane == 0) atomicAdd(cnt + d, 1.0f);
}

// ---------------- inner product core on pre-split smem tiles ----------------
__device__ __forceinline__ void mma_block(
    const float* Ahi, const float* Alo, const float* Bhi, const float* Blo,
    int warp_m, int warp_n, FragC acc[4][2])
{
#pragma unroll
    for (int kk = 0; kk < 32; kk += 8) {
        FragB bh[2], bl[2];
#pragma unroll
        for (int nt = 0; nt < 2; nt++) {
            int brow = warp_n * 32 + nt * 16;
            wmma::load_matrix_sync(bh[nt], &Bhi[brow * TSS + kk], TSS);
            wmma::load_matrix_sync(bl[nt], &Blo[brow * TSS + kk], TSS);
        }
#pragma unroll
        for (int mt = 0; mt < 4; mt++) {
            int arow = warp_m * 64 + mt * 16;
            FragA ah, al;
            wmma::load_matrix_sync(ah, &Ahi[arow * TSS + kk], TSS);
            wmma::load_matrix_sync(al, &Alo[arow * TSS + kk], TSS);
#pragma unroll
            for (int nt = 0; nt < 2; nt++) {
                wmma::mma_sync(acc[mt][nt], ah, bh[nt], acc[mt][nt]);
                wmma::mma_sync(acc[mt][nt], al, bh[nt], acc[mt][nt]);
                wmma::mma_sync(acc[mt][nt], ah, bl[nt], acc[mt][nt]);
            }
        }
    }
}

// ---------------- input projection: C = relu(A[N,256] @ W[128,256]^T + b) ----------
__global__ __launch_bounds__(256, 2) void proj_mma_kernel(
    const float* __restrict__ A, const float* __restrict__ W,
    const float* __restrict__ bias, int N, int to_user)
{
    extern __shared__ float sm[];
    float* Ahi = sm;
    float* Alo = sm + 128 * TSS;
    float* Bhi = sm + 2 * 128 * TSS;
    float* Blo = sm + 3 * 128 * TSS;
    float* Cs  = sm;   // epilogue reuse

    float* C = to_user ? g_hu : g_hi;
    int tid = threadIdx.x;
    int row0 = blockIdx.x * 128;
    int wid = tid >> 5;
    int warp_m = wid & 1;
    int warp_n = wid >> 1;

    FragC acc[4][2];
#pragma unroll
    for (int mt = 0; mt < 4; mt++)
#pragma unroll
        for (int nt = 0; nt < 2; nt++) wmma::fill_fragment(acc[mt][nt], 0.f);

    for (int k0 = 0; k0 < IN_DIM; k0 += 32) {
#pragma unroll
        for (int i = 0; i < 4; i++) {
            int idx = tid + i * 256;
            int r = idx >> 3;
            int q = (idx & 7) * 4;
            int gr = row0 + r;
            float4 v = (gr < N) ? *(const float4*)(A + (size_t)gr * IN_DIM + k0 + q)
                                : make_float4(0.f, 0.f, 0.f, 0.f);
            float4 w = *(const float4*)(W + (size_t)r * IN_DIM + k0 + q);
            float4 vh, vl, wh, wl;
            split4(v, vh, vl);
            split4(w, wh, wl);
            *(float4*)&Ahi[r * TSS + q] = vh;
            *(float4*)&Alo[r * TSS + q] = vl;
            *(float4*)&Bhi[r * TSS + q] = wh;
            *(float4*)&Blo[r * TSS + q] = wl;
        }
        __syncthreads();
        mma_block(Ahi, Alo, Bhi, Blo, warp_m, warp_n, acc);
        __syncthreads();
    }

#pragma unroll
    for (int mt = 0; mt < 4; mt++)
#pragma unroll
        for (int nt = 0; nt < 2; nt++)
            wmma::store_matrix_sync(&Cs[(warp_m * 64 + mt * 16) * CS + warp_n * 32 + nt * 16],
                                    acc[mt][nt], CS, wmma::mem_row_major);
    __syncthreads();
#pragma unroll
    for (int i = 0; i < 16; i++) {
        int idx = tid + i * 256;
        int r = idx >> 5;
        int c4 = (idx & 31) * 4;
        int gr = row0 + r;
        if (gr < N) {
            float4 v = *(float4*)&Cs[r * CS + c4];
            float4 b = *(const float4*)(bias + c4);
            v.x = fmaxf(v.x + b.x, 0.f);
            v.y = fmaxf(v.y + b.y, 0.f);
            v.z = fmaxf(v.z + b.z, 0.f);
            v.w = fmaxf(v.w + b.w, 0.f);
            *(float4*)(C + (size_t)gr * HD + c4) = v;
        }
    }
}

// ---------------- SAGE combine + residual + LN (+relu), fully fused ----------------
// out = LN(h + (agg*rinv) @ WL^T + h @ WR^T + BL)
__global__ __launch_bounds__(256, 2) void sage_mma_kernel(
    const float* __restrict__ WL, const float* __restrict__ WR,
    const float* __restrict__ BL,
    const float* __restrict__ gamma, const float* __restrict__ beta,
    float* final_out, int N, int to_item, int relu)
{
    extern __shared__ float sm[];
    float* Ahi = sm;
    float* Alo = sm + 128 * TSS;
    float* Bhi = sm + 2 * 128 * TSS;
    float* Blo = sm + 3 * 128 * TSS;
    float* Cs  = sm;

    const float* A0  = to_item ? g_agg_i : g_agg_u;
    const float* CNT = to_item ? g_cnt_i : g_cnt_u;
    float* H         = to_item ? g_hi : g_hu;

    int tid = threadIdx.x;
    int row0 = blockIdx.x * 128;
    int wid = tid >> 5;
    int lane = tid & 31;
    int warp_m = wid & 1;
    int warp_n = wid >> 1;

    FragC acc[4][2];
#pragma unroll
    for (int mt = 0; mt < 4; mt++)
#pragma unroll
        for (int nt = 0; nt < 2; nt++) wmma::fill_fragment(acc[mt][nt], 0.f);

    for (int k0 = 0; k0 < 256; k0 += 32) {
#pragma unroll
        for (int i = 0; i < 4; i++) {
            int idx = tid + i * 256;
            int r = idx >> 3;
            int q = (idx & 7) * 4;
            int gr = row0 + r;
            float4 v, w;
            if (k0 < 128) {
                int c = k0 + q;
                if (gr < N) {
                    v = *(const float4*)(A0 + (size_t)gr * HD + c);
                    float s = 1.0f / fmaxf(CNT[gr], 1.0f);
                    v.x *= s; v.y *= s; v.z *= s; v.w *= s;
                } else v = make_float4(0.f, 0.f, 0.f, 0.f);
                w = *(const float4*)(WL + (size_t)r * HD + c);
            } else {
                int c = k0 - 128 + q;
                v = (gr < N) ? *(const float4*)(H + (size_t)gr * HD + c)
                             : make_float4(0.f, 0.f, 0.f, 0.f);
                w = *(const float4*)(WR + (size_t)r * HD + c);
            }
            float4 vh, vl, wh, wl;
            split4(v, vh, vl);
            split4(w, wh, wl);
            *(float4*)&Ahi[r * TSS + q] = vh;
            *(float4*)&Alo[r * TSS + q] = vl;
            *(float4*)&Bhi[r * TSS + q] = wh;
            *(float4*)&Blo[r * TSS + q] = wl;
        }
        __syncthreads();
        mma_block(Ahi, Alo, Bhi, Blo, warp_m, warp_n, acc);
        __syncthreads();
    }

#pragma unroll
    for (int mt = 0; mt < 4; mt++)
#pragma unroll
        for (int nt = 0; nt < 2; nt++)
            wmma::store_matrix_sync(&Cs[(warp_m * 64 + mt * 16) * CS + warp_n * 32 + nt * 16],
                                    acc[mt][nt], CS, wmma::mem_row_major);
    __syncthreads();

    // fused residual + LN (+relu). Each warp owns rows wid, wid+8, ...
    float4 bv  = *(const float4*)(BL + lane * 4);
    float4 gv  = *(const float4*)(gamma + lane * 4);
    float4 btv = *(const float4*)(beta + lane * 4);
#pragma unroll
    for (int rr = wid; rr < 128; rr += 8) {
        int gr = row0 + rr;
        if (gr >= N) continue;
        float4 cvv = *(float4*)&Cs[rr * CS + lane * 4];
        float4 hv = *(const float4*)(H + (size_t)gr * HD + lane * 4);
        float v0 = cvv.x + bv.x + hv.x;
        float v1 = cvv.y + bv.y + hv.y;
        float v2 = cvv.z + bv.z + hv.z;
        float v3 = cvv.w + bv.w + hv.w;

        float s = v0 + v1 + v2 + v3;
#pragma unroll
        for (int off = 16; off; off >>= 1) s += __shfl_xor_sync(0xffffffffu, s, off);
        float mu = s * (1.0f / 128.0f);
        v0 -= mu; v1 -= mu; v2 -= mu; v3 -= mu;

        float q = v0 * v0 + v1 * v1 + v2 * v2 + v3 * v3;
#pragma unroll
        for (int off = 16; off; off >>= 1) q += __shfl_xor_sync(0xffffffffu, q, off);
        float rs = rsqrtf(q * (1.0f / 128.0f) + LN_EPS);

        float o0 = v0 * rs * gv.x + btv.x;
        float o1 = v1 * rs * gv.y + btv.y;
        float o2 = v2 * rs * gv.z + btv.z;
        float o3 = v3 * rs * gv.w + btv.w;
        if (relu) {
            o0 = fmaxf(o0, 0.f); o1 = fmaxf(o1, 0.f);
            o2 = fmaxf(o2, 0.f); o3 = fmaxf(o3, 0.f);
        }
        float* dst = final_out ? (final_out + (size_t)gr * HD) : (H + (size_t)gr * HD);
        ((float4*)dst)[lane] = make_float4(o0, o1, o2, o3);
    }
}

// ---------------- launch ----------------
extern "C" void kernel_launch(void* const* d_in, const int* in_sizes, int n_in,
                              void* d_out, int out_size)
{
    const float* x_user = (const float*)d_in[0];
    const float* x_item = (const float*)d_in[1];
    const int* ei_rates = (const int*)d_in[2];   // [2, E]
    const int* ei_rev   = (const int*)d_in[3];
    const float* puw = (const float*)d_in[4];
    const float* pub = (const float*)d_in[5];
    const float* piw = (const float*)d_in[6];
    const float* pib = (const float*)d_in[7];
    const float* lnug = (const float*)d_in[8];
    const float* lnub = (const float*)d_in[9];
    const float* lnig = (const float*)d_in[10];
    const float* lnib = (const float*)d_in[11];

    int N = in_sizes[0] / IN_DIM;    // 100000
    int E = in_sizes[2] / 2;         // 600000
    float* out = (float*)d_out;

    const int SMEM = 4 * 128 * TSS * sizeof(float);   // 73728 B
    static int configured = 0;
    if (!configured) {
        cudaFuncSetAttribute(proj_mma_kernel, cudaFuncAttributeMaxDynamicSharedMemorySize, SMEM);
        cudaFuncSetAttribute(sage_mma_kernel, cudaFuncAttributeMaxDynamicSharedMemorySize, SMEM);
        configured = 1;
    }

    dim3 gGemm((N + 127) / 128);
    int scatterBlocks = (E * 32 + 255) / 256;

    proj_mma_kernel<<<gGemm, 256, SMEM>>>(x_user, puw, pub, N, 1);
    proj_mma_kernel<<<gGemm, 256, SMEM>>>(x_item, piw, pib, N, 0);

    for (int l = 0; l < 2; l++) {
        const float* rwl = (const float*)d_in[12 + l * 6 + 0];
        const float* rbl = (const float*)d_in[12 + l * 6 + 1];
        const float* rwr = (const float*)d_in[12 + l * 6 + 2];
        const float* vwl = (const float*)d_in[12 + l * 6 + 3];
        const float* vbl = (const float*)d_in[12 + l * 6 + 4];
        const float* vwr = (const float*)d_in[12 + l * 6 + 5];

        zero_layer_kernel<<<2048, 256>>>();
        scatter_kernel<<<scatterBlocks, 256>>>(ei_rates, ei_rates + E, E, 1); // user -> item
        scatter_kernel<<<scatterBlocks, 256>>>(ei_rev, ei_rev + E, E, 0);     // item -> user

        int relu = (l == 0) ? 1 : 0;
        float* ou = (l == 1) ? out : (float*)0;
        float* oi = (l == 1) ? out + (size_t)N * HD : (float*)0;
        sage_mma_kernel<<<gGemm, 256, SMEM>>>(rwl, rwr, rbl, lnig, lnib, oi, N, 1, relu);
        sage_mma_kernel<<<gGemm, 256, SMEM>>>(vwl, vwr, vbl, lnug, lnub, ou, N, 0, relu);
    }
}

// round 13
// speedup vs baseline: 1.9791x; 1.9791x over previous
#include <cuda_runtime.h>
#include <cuda_bf16.h>
#include <mma.h>
#include <cstdint>
#include <cstddef>

using namespace nvcuda;

#define N_NODES 100000
#define HD 128
#define IN_DIM 256
#define LN_EPS 1e-5f

#define TSB 40     // bf16 smem tile stride (elements): 32 data + 8 pad
#define CS 132     // epilogue C stride (floats)
#define SMEM_TOTAL (128 * CS * 4)   // 67584 B (covers 4 bf16 tiles = 40960 B too)

// smem byte offsets of the 4 bf16 tiles (each 128 x TSB bf16 = 10240 B)
#define O_AHI 0
#define O_ALO 10240
#define O_BHI 20480
#define O_BLO 30720

// ---------------- scratch (device globals; no allocation allowed) ----------------
__device__ __align__(16) float g_hu[(size_t)N_NODES * HD];
__device__ __align__(16) float g_hi[(size_t)N_NODES * HD];
__device__ __align__(16) float g_agg_u[(size_t)N_NODES * HD];
__device__ __align__(16) float g_agg_i[(size_t)N_NODES * HD];
__device__ __align__(16) float g_cnt_u[N_NODES];
__device__ __align__(16) float g_cnt_i[N_NODES];

typedef wmma::fragment<wmma::matrix_a, 16, 16, 16, __nv_bfloat16, wmma::row_major> FragA;
typedef wmma::fragment<wmma::matrix_b, 16, 16, 16, __nv_bfloat16, wmma::col_major> FragB;
typedef wmma::fragment<wmma::accumulator, 16, 16, 16, float> FragC;

// split 8 f32 into packed bf16 hi/lo words
__device__ __forceinline__ void cvt8(const float* a, uint4& hp, uint4& lp) {
    uint32_t h[4], l[4];
#pragma unroll
    for (int j = 0; j < 4; j++) {
        float x0 = a[2 * j], x1 = a[2 * j + 1];
        __nv_bfloat16 h0 = __float2bfloat16_rn(x0);
        __nv_bfloat16 h1 = __float2bfloat16_rn(x1);
        __nv_bfloat16 l0 = __float2bfloat16_rn(x0 - __bfloat162float(h0));
        __nv_bfloat16 l1 = __float2bfloat16_rn(x1 - __bfloat162float(h1));
        h[j] = ((uint32_t)__bfloat16_as_ushort(h1) << 16) | (uint32_t)__bfloat16_as_ushort(h0);
        l[j] = ((uint32_t)__bfloat16_as_ushort(l1) << 16) | (uint32_t)__bfloat16_as_ushort(l0);
    }
    hp = make_uint4(h[0], h[1], h[2], h[3]);
    lp = make_uint4(l[0], l[1], l[2], l[3]);
}

// ---------------- inner product core on pre-split bf16 smem tiles ----------------
__device__ __forceinline__ void mma_block(
    const __nv_bfloat16* Ahi, const __nv_bfloat16* Alo,
    const __nv_bfloat16* Bhi, const __nv_bfloat16* Blo,
    int warp_m, int warp_n, FragC acc[4][2])
{
#pragma unroll
    for (int kk = 0; kk < 32; kk += 16) {
        FragB bh[2], bl[2];
#pragma unroll
        for (int nt = 0; nt < 2; nt++) {
            int brow = warp_n * 32 + nt * 16;
            wmma::load_matrix_sync(bh[nt], &Bhi[brow * TSB + kk], TSB);
            wmma::load_matrix_sync(bl[nt], &Blo[brow * TSB + kk], TSB);
        }
#pragma unroll
        for (int mt = 0; mt < 4; mt++) {
            int arow = warp_m * 64 + mt * 16;
            FragA ah, al;
            wmma::load_matrix_sync(ah, &Ahi[arow * TSB + kk], TSB);
            wmma::load_matrix_sync(al, &Alo[arow * TSB + kk], TSB);
#pragma unroll
            for (int nt = 0; nt < 2; nt++) {
                wmma::mma_sync(acc[mt][nt], ah, bh[nt], acc[mt][nt]);
                wmma::mma_sync(acc[mt][nt], al, bh[nt], acc[mt][nt]);
                wmma::mma_sync(acc[mt][nt], ah, bl[nt], acc[mt][nt]);
            }
        }
    }
}

// ---------------- edge scatter: warp per edge, vector RED per lane ----------------
__global__ __launch_bounds__(256) void scatter_kernel(
    const int* __restrict__ src, const int* __restrict__ dst, int E, int to_item)
{
    const float* h = to_item ? g_hu : g_hi;
    float* agg     = to_item ? g_agg_i : g_agg_u;
    float* cnt     = to_item ? g_cnt_i : g_cnt_u;

    int w = (blockIdx.x * blockDim.x + threadIdx.x) >> 5;
    int lane = threadIdx.x & 31;
    if (w >= E) return;
    int s = src[w];
    int d = dst[w];
    float4 v = ((const float4*)(h + (size_t)s * HD))[lane];
    float* ap = agg + (size_t)d * HD + lane * 4;
    asm volatile("red.global.add.v4.f32 [%0], {%1, %2, %3, %4};"
                 :: "l"(ap), "f"(v.x), "f"(v.y), "f"(v.z), "f"(v.w) : "memory");
    if (lane == 0) atomicAdd(cnt + d, 1.0f);
}

// ---------------- input projection: C = relu(X @ W^T + b); zero agg/cnt ----------
__global__ __launch_bounds__(256, 2) void proj_mma_kernel(
    const float* __restrict__ X, const float* __restrict__ W,
    const float* __restrict__ bias, int N, int to_user)
{
    extern __shared__ char smem[];
    __nv_bfloat16* Ahi = (__nv_bfloat16*)(smem + O_AHI);
    __nv_bfloat16* Alo = (__nv_bfloat16*)(smem + O_ALO);
    __nv_bfloat16* Bhi = (__nv_bfloat16*)(smem + O_BHI);
    __nv_bfloat16* Blo = (__nv_bfloat16*)(smem + O_BLO);
    float* Cs = (float*)smem;

    float* C    = to_user ? g_hu : g_hi;
    float* ZAGG = to_user ? g_agg_u : g_agg_i;
    float* ZCNT = to_user ? g_cnt_u : g_cnt_i;

    int tid = threadIdx.x;
    int row0 = blockIdx.x * 128;
    int wid = tid >> 5;
    int warp_m = wid & 1;
    int warp_n = wid >> 1;

    FragC acc[4][2];
#pragma unroll
    for (int mt = 0; mt < 4; mt++)
#pragma unroll
        for (int nt = 0; nt < 2; nt++) wmma::fill_fragment(acc[mt][nt], 0.f);

    for (int k0 = 0; k0 < IN_DIM; k0 += 32) {
        float av[2][8], wv[2][8];
        int rr[2], qq[2];
#pragma unroll
        for (int i = 0; i < 2; i++) {
            int idx = tid + i * 256;
            int r = idx >> 2, q8 = (idx & 3) * 8;
            rr[i] = r; qq[i] = q8;
            int gr = row0 + r;
            if (gr < N) {
                const float* as = X + (size_t)gr * IN_DIM + k0 + q8;
                float4 p0 = *(const float4*)as;
                float4 p1 = *(const float4*)(as + 4);
                av[i][0] = p0.x; av[i][1] = p0.y; av[i][2] = p0.z; av[i][3] = p0.w;
                av[i][4] = p1.x; av[i][5] = p1.y; av[i][6] = p1.z; av[i][7] = p1.w;
            } else {
#pragma unroll
                for (int j = 0; j < 8; j++) av[i][j] = 0.f;
            }
            const float* ws = W + (size_t)r * IN_DIM + k0 + q8;
            float4 w0 = *(const float4*)ws;
            float4 w1 = *(const float4*)(ws + 4);
            wv[i][0] = w0.x; wv[i][1] = w0.y; wv[i][2] = w0.z; wv[i][3] = w0.w;
            wv[i][4] = w1.x; wv[i][5] = w1.y; wv[i][6] = w1.z; wv[i][7] = w1.w;
        }
        __syncthreads();   // previous mma_block done reading tiles
#pragma unroll
        for (int i = 0; i < 2; i++) {
            uint4 hp, lp;
            cvt8(av[i], hp, lp);
            *(uint4*)&Ahi[rr[i] * TSB + qq[i]] = hp;
            *(uint4*)&Alo[rr[i] * TSB + qq[i]] = lp;
            cvt8(wv[i], hp, lp);
            *(uint4*)&Bhi[rr[i] * TSB + qq[i]] = hp;
            *(uint4*)&Blo[rr[i] * TSB + qq[i]] = lp;
        }
        __syncthreads();
        mma_block(Ahi, Alo, Bhi, Blo, warp_m, warp_n, acc);
    }
    __syncthreads();

#pragma unroll
    for (int mt = 0; mt < 4; mt++)
#pragma unroll
        for (int nt = 0; nt < 2; nt++)
            wmma::store_matrix_sync(&Cs[(warp_m * 64 + mt * 16) * CS + warp_n * 32 + nt * 16],
                                    acc[mt][nt], CS, wmma::mem_row_major);
    __syncthreads();
#pragma unroll
    for (int i = 0; i < 16; i++) {
        int idx = tid + i * 256;
        int r = idx >> 5;
        int c4 = (idx & 31) * 4;
        int gr = row0 + r;
        if (gr < N) {
            float4 v = *(float4*)&Cs[r * CS + c4];
            float4 b = *(const float4*)(bias + c4);
            v.x = fmaxf(v.x + b.x, 0.f);
            v.y = fmaxf(v.y + b.y, 0.f);
            v.z = fmaxf(v.z + b.z, 0.f);
            v.w = fmaxf(v.w + b.w, 0.f);
            *(float4*)(C + (size_t)gr * HD + c4) = v;
            *(float4*)(ZAGG + (size_t)gr * HD + c4) = make_float4(0.f, 0.f, 0.f, 0.f);
            if (c4 == 0) ZCNT[gr] = 0.f;
        }
    }
}

// ---------------- SAGE combine + residual + LN (+relu); opt zero agg ----------
// out = LN(h + (agg/max(cnt,1)) @ WL^T + h @ WR^T + BL)
__global__ __launch_bounds__(256, 2) void sage_mma_kernel(
    const float* __restrict__ WL, const float* __restrict__ WR,
    const float* __restrict__ BL,
    const float* __restrict__ gamma, const float* __restrict__ beta,
    float* final_out, int N, int to_item, int relu, int zero_next)
{
    extern __shared__ char smem[];
    __nv_bfloat16* Ahi = (__nv_bfloat16*)(smem + O_AHI);
    __nv_bfloat16* Alo = (__nv_bfloat16*)(smem + O_ALO);
    __nv_bfloat16* Bhi = (__nv_bfloat16*)(smem + O_BHI);
    __nv_bfloat16* Blo = (__nv_bfloat16*)(smem + O_BLO);
    float* Cs = (float*)smem;

    const float* AGG = to_item ? g_agg_i : g_agg_u;
    const float* CNT = to_item ? g_cnt_i : g_cnt_u;
    float* H         = to_item ? g_hi : g_hu;
    float* ZCNT      = to_item ? g_cnt_i : g_cnt_u;

    int tid = threadIdx.x;
    int row0 = blockIdx.x * 128;
    int wid = tid >> 5;
    int lane = tid & 31;
    int warp_m = wid & 1;
    int warp_n = wid >> 1;

    FragC acc[4][2];
#pragma unroll
    for (int mt = 0; mt < 4; mt++)
#pragma unroll
        for (int nt = 0; nt < 2; nt++) wmma::fill_fragment(acc[mt][nt], 0.f);

    for (int c = 0; c < 8; c++) {
        float av[2][8], wv[2][8];
        int rr[2], qq[2];
#pragma unroll
        for (int i = 0; i < 2; i++) {
            int idx = tid + i * 256;
            int r = idx >> 2, q8 = (idx & 3) * 8;
            rr[i] = r; qq[i] = q8;
            int gr = row0 + r;
            if (gr < N) {
                float scale = 1.f;
                const float* as;
                if (c < 4) {
                    as = AGG + (size_t)gr * HD + c * 32 + q8;
                    scale = 1.0f / fmaxf(CNT[gr], 1.0f);
                } else {
                    as = H + (size_t)gr * HD + (c - 4) * 32 + q8;
                }
                float4 p0 = *(const float4*)as;
                float4 p1 = *(const float4*)(as + 4);
                av[i][0] = p0.x * scale; av[i][1] = p0.y * scale;
                av[i][2] = p0.z * scale; av[i][3] = p0.w * scale;
                av[i][4] = p1.x * scale; av[i][5] = p1.y * scale;
                av[i][6] = p1.z * scale; av[i][7] = p1.w * scale;
            } else {
#pragma unroll
                for (int j = 0; j < 8; j++) av[i][j] = 0.f;
            }
            const float* ws = (c < 4 ? WL : WR) + (size_t)r * HD + (c & 3) * 32 + q8;
            float4 w0 = *(const float4*)ws;
            float4 w1 = *(const float4*)(ws + 4);
            wv[i][0] = w0.x; wv[i][1] = w0.y; wv[i][2] = w0.z; wv[i][3] = w0.w;
            wv[i][4] = w1.x; wv[i][5] = w1.y; wv[i][6] = w1.z; wv[i][7] = w1.w;
        }
        __syncthreads();
#pragma unroll
        for (int i = 0; i < 2; i++) {
            uint4 hp, lp;
            cvt8(av[i], hp, lp);
            *(uint4*)&Ahi[rr[i] * TSB + qq[i]] = hp;
            *(uint4*)&Alo[rr[i] * TSB + qq[i]] = lp;
            cvt8(wv[i], hp, lp);
            *(uint4*)&Bhi[rr[i] * TSB + qq[i]] = hp;
            *(uint4*)&Blo[rr[i] * TSB + qq[i]] = lp;
        }
        __syncthreads();
        mma_block(Ahi, Alo, Bhi, Blo, warp_m, warp_n, acc);
    }
    __syncthreads();

#pragma unroll
    for (int mt = 0; mt < 4; mt++)
#pragma unroll
        for (int nt = 0; nt < 2; nt++)
            wmma::store_matrix_sync(&Cs[(warp_m * 64 + mt * 16) * CS + warp_n * 32 + nt * 16],
                                    acc[mt][nt], CS, wmma::mem_row_major);
    __syncthreads();

    // fused residual + LN (+relu) + optional zeroing; warp per row (rows wid, wid+8, ...)
    float4 bv  = *(const float4*)(BL + lane * 4);
    float4 gv  = *(const float4*)(gamma + lane * 4);
    float4 btv = *(const float4*)(beta + lane * 4);
    float* ZAGGp = to_item ? g_agg_i : g_agg_u;
#pragma unroll
    for (int rrow = wid; rrow < 128; rrow += 8) {
        int gr = row0 + rrow;
        if (gr >= N) continue;
        float4 cvv = *(float4*)&Cs[rrow * CS + lane * 4];
        float4 hv = *(const float4*)(H + (size_t)gr * HD + lane * 4);
        float v0 = cvv.x + bv.x + hv.x;
        float v1 = cvv.y + bv.y + hv.y;
        float v2 = cvv.z + bv.z + hv.z;
        float v3 = cvv.w + bv.w + hv.w;

        float s = v0 + v1 + v2 + v3;
#pragma unroll
        for (int off = 16; off; off >>= 1) s += __shfl_xor_sync(0xffffffffu, s, off);
        float mu = s * (1.0f / 128.0f);
        v0 -= mu; v1 -= mu; v2 -= mu; v3 -= mu;

        float q = v0 * v0 + v1 * v1 + v2 * v2 + v3 * v3;
#pragma unroll
        for (int off = 16; off; off >>= 1) q += __shfl_xor_sync(0xffffffffu, q, off);
        float rs = rsqrtf(q * (1.0f / 128.0f) + LN_EPS);

        float o0 = v0 * rs * gv.x + btv.x;
        float o1 = v1 * rs * gv.y + btv.y;
        float o2 = v2 * rs * gv.z + btv.z;
        float o3 = v3 * rs * gv.w + btv.w;
        if (relu) {
            o0 = fmaxf(o0, 0.f); o1 = fmaxf(o1, 0.f);
            o2 = fmaxf(o2, 0.f); o3 = fmaxf(o3, 0.f);
        }
        float* dst = final_out ? (final_out + (size_t)gr * HD) : (H + (size_t)gr * HD);
        ((float4*)dst)[lane] = make_float4(o0, o1, o2, o3);
        if (zero_next) {
            ((float4*)(ZAGGp + (size_t)gr * HD))[lane] = make_float4(0.f, 0.f, 0.f, 0.f);
            if (lane == 0) ZCNT[gr] = 0.f;
        }
    }
}

// ---------------- launch ----------------
extern "C" void kernel_launch(void* const* d_in, const int* in_sizes, int n_in,
                              void* d_out, int out_size)
{
    const float* x_user = (const float*)d_in[0];
    const float* x_item = (const float*)d_in[1];
    const int* ei_rates = (const int*)d_in[2];   // [2, E]
    const int* ei_rev   = (const int*)d_in[3];
    const float* puw = (const float*)d_in[4];
    const float* pub = (const float*)d_in[5];
    const float* piw = (const float*)d_in[6];
    const float* pib = (const float*)d_in[7];
    const float* lnug = (const float*)d_in[8];
    const float* lnub = (const float*)d_in[9];
    const float* lnig = (const float*)d_in[10];
    const float* lnib = (const float*)d_in[11];

    int N = in_sizes[0] / IN_DIM;    // 100000
    int E = in_sizes[2] / 2;         // 600000
    float* out = (float*)d_out;

    static int configured = 0;
    if (!configured) {
        cudaFuncSetAttribute(proj_mma_kernel, cudaFuncAttributeMaxDynamicSharedMemorySize, SMEM_TOTAL);
        cudaFuncSetAttribute(sage_mma_kernel, cudaFuncAttributeMaxDynamicSharedMemorySize, SMEM_TOTAL);
        configured = 1;
    }

    dim3 gGemm((N + 127) / 128);
    int scatterBlocks = (E * 32 + 255) / 256;

    // projections (relu) + zero agg/cnt for layer-0 scatter
    proj_mma_kernel<<<gGemm, 256, SMEM_TOTAL>>>(x_user, puw, pub, N, 1);
    proj_mma_kernel<<<gGemm, 256, SMEM_TOTAL>>>(x_item, piw, pib, N, 0);

    for (int l = 0; l < 2; l++) {
        const float* rwl = (const float*)d_in[12 + l * 6 + 0];
        const float* rbl = (const float*)d_in[12 + l * 6 + 1];
        const float* rwr = (const float*)d_in[12 + l * 6 + 2];
        const float* vwl = (const float*)d_in[12 + l * 6 + 3];
        const float* vbl = (const float*)d_in[12 + l * 6 + 4];
        const float* vwr = (const float*)d_in[12 + l * 6 + 5];

        scatter_kernel<<<scatterBlocks, 256>>>(ei_rates, ei_rates + E, E, 1); // user -> item
        scatter_kernel<<<scatterBlocks, 256>>>(ei_rev, ei_rev + E, E, 0);     // item -> user

        int relu = (l == 0) ? 1 : 0;
        int zero_next = (l == 0) ? 1 : 0;
        float* ou = (l == 1) ? out : (float*)0;
        float* oi = (l == 1) ? out + (size_t)N * HD : (float*)0;
        sage_mma_kernel<<<gGemm, 256, SMEM_TOTAL>>>(rwl, rwr, rbl, lnig, lnib, oi, N, 1, relu, zero_next);
        sage_mma_kernel<<<gGemm, 256, SMEM_TOTAL>>>(vwl, vwr, vbl, lnug, lnub, ou, N, 0, relu, zero_next);
    }
}